// round 16
// baseline (speedup 1.0000x reference)
#include <cuda_runtime.h>
#include <cuda_fp16.h>
#include <cstdint>
#include <math.h>

#define T_  4
#define B_  32
#define N_  196
#define C_  512
#define H_  8
#define HD  64
#define M_  (T_*B_*N_)          // 25088
#define ELEMS ((size_t)M_*C_)   // 12,845,056
#define BNC ((size_t)B_*N_*C_)
#define WELEMS ((size_t)C_*C_)

struct P3f { const float* p[3]; };
struct P3u { unsigned int* p[3]; };

// ---------------- scratch (device globals) ----------------
__device__ float g_y[3*ELEMS];                  // q,k,v GEMM outputs (proj reuses slot 0)
__device__ unsigned short g_attn16[ELEMS];      // attention integer accumulators (exact)
__device__ __half g_x0[ELEMS], g_x1[ELEMS];     // x fp16 splits
__device__ __half g_pA[ELEMS];                  // attn spikes (fp16, exact 0/1)
__device__ __half g_w0[3*WELEMS], g_w1[3*WELEMS];  // weight fp16 splits
__device__ unsigned int g_qbits[(size_t)T_*B_*H_*N_*2];
__device__ unsigned int g_kbits[(size_t)T_*B_*H_*N_*2];
__device__ unsigned int g_vbits[(size_t)T_*B_*H_*N_*2];
__device__ double g_sum[4*C_];
__device__ double g_sumsq[4*C_];
__device__ float g_meanf[4*C_];
__device__ float g_rstdf[4*C_];

// ---------------- helpers ----------------
static __device__ __forceinline__ uint32_t s2u(const void* p) {
    uint32_t a;
    asm("{ .reg .u64 t; cvta.to.shared.u64 t, %1; cvt.u32.u64 %0, t; }" : "=r"(a) : "l"(p));
    return a;
}
static __device__ __forceinline__ void cpa16(uint32_t dst, const void* src) {
    asm volatile("cp.async.cg.shared.global [%0], [%1], 16;" :: "r"(dst), "l"(src));
}
static __device__ __forceinline__ void ldmx4(uint32_t* r, uint32_t addr) {
    asm volatile("ldmatrix.sync.aligned.m8n8.x4.shared.b16 {%0,%1,%2,%3}, [%4];"
                 : "=r"(r[0]), "=r"(r[1]), "=r"(r[2]), "=r"(r[3]) : "r"(addr));
}
static __device__ __forceinline__ void mma16816(float* c, const uint32_t* a,
                                                const uint32_t* b) {
    asm volatile(
        "mma.sync.aligned.m16n8k16.row.col.f32.f16.f16.f32 "
        "{%0,%1,%2,%3}, {%4,%5,%6,%7}, {%8,%9}, {%0,%1,%2,%3};"
        : "+f"(c[0]), "+f"(c[1]), "+f"(c[2]), "+f"(c[3])
        : "r"(a[0]), "r"(a[1]), "r"(a[2]), "r"(a[3]), "r"(b[0]), "r"(b[1]));
}

// ---------------- fp16 split-GEMM: 128x64 CTA tile for 3 CTAs/SM occupancy ----------------
// Y[branch][M,512] = A0@B0^T + A0@B1^T + (doA1? A1@B0^T) + bias[branch]
// 128m x 64n tile, BK=32, 256 thr, 8 warps (4m x 2n, 32x32 warp tile),
// cp.async double buffer, phase-staggered k, fused BN statistics epilogue.
#define APAD 40                         // halfs per smem row (80 B)
#define A_TILE (128*APAD)               // 5120 halfs
#define B_TILE (64*APAD)                // 2560 halfs
#define STAGE_H (2*A_TILE + 2*B_TILE)   // 15360 halfs
#define GSMEM (2*(size_t)STAGE_H*sizeof(__half))   // 61440 B

__global__ __launch_bounds__(256, 3) void gemm_fp16_mma(
    const __half* __restrict__ A0, const __half* __restrict__ A1,
    const __half* __restrict__ W0b, const __half* __restrict__ W1b,
    P3f biasP, float* __restrict__ Yb, int doA1, int slotbase)
{
    extern __shared__ __half sm[];
    const int tid = threadIdx.x;
    const int wid = tid >> 5, lane = tid & 31;
    const int bx = blockIdx.x;
    const int branch = bx >> 3;
    const int m0 = blockIdx.y * 128, n0 = (bx & 7) * 64;
    const int warp_m = wid & 3, warp_n = wid >> 2;
    const float* bias = biasP.p[branch];
    float* Y = Yb + (size_t)branch * ELEMS;
    const int slot = slotbase + branch;
    const int phase = ((bx + blockIdx.y) & 1) * 8;

    const __half* gA0 = A0 + (size_t)m0 * C_;
    const __half* gA1 = A1 + (size_t)m0 * C_;
    const __half* gB0 = W0b + (size_t)branch * WELEMS + (size_t)n0 * C_;
    const __half* gB1 = W1b + (size_t)branch * WELEMS + (size_t)n0 * C_;

    // load indices: A 128 rows x 32 halfs (2 chunks/thread), B 64 rows (1 chunk/thread)
    const int arow = tid >> 1, ac = (tid & 1) * 8;        // A chunk offs: ac, ac+16
    const int brow = tid >> 2, bc = (tid & 3) * 8;

    // prologue: first chunk at k = phase*32
    {
        int k0 = phase * 32;
        uint32_t d;
        d = s2u(sm + arow * APAD + ac);
        cpa16(d, gA0 + (size_t)arow * C_ + k0 + ac);
        cpa16(d + 32, gA0 + (size_t)arow * C_ + k0 + ac + 16);
        if (doA1) {
            d = s2u(sm + A_TILE + arow * APAD + ac);
            cpa16(d, gA1 + (size_t)arow * C_ + k0 + ac);
            cpa16(d + 32, gA1 + (size_t)arow * C_ + k0 + ac + 16);
        }
        d = s2u(sm + 2 * A_TILE + brow * APAD + bc);
        cpa16(d, gB0 + (size_t)brow * C_ + k0 + bc);
        d = s2u(sm + 2 * A_TILE + B_TILE + brow * APAD + bc);
        cpa16(d, gB1 + (size_t)brow * C_ + k0 + bc);
    }
    asm volatile("cp.async.commit_group;");

    float acc[2][4][4];
#pragma unroll
    for (int i = 0; i < 2; i++)
#pragma unroll
        for (int j = 0; j < 4; j++)
#pragma unroll
            for (int k = 0; k < 4; k++) acc[i][j][k] = 0.f;

    const int rB4 = warp_n * 32 + ((lane >> 4) << 3) + (lane & 7);
    const int colB4base = (((lane >> 3) & 1) << 3);

    for (int kcc = 0; kcc < 16; kcc++) {
        asm volatile("cp.async.wait_group 0;");
        __syncthreads();
        const int s = kcc & 1;
        if (kcc + 1 < 16) {
            int k0 = ((kcc + 1 + phase) & 15) * 32;
            const __half* base = sm + (s ^ 1) * STAGE_H;
            uint32_t d;
            d = s2u(base + arow * APAD + ac);
            cpa16(d, gA0 + (size_t)arow * C_ + k0 + ac);
            cpa16(d + 32, gA0 + (size_t)arow * C_ + k0 + ac + 16);
            if (doA1) {
                d = s2u(base + A_TILE + arow * APAD + ac);
                cpa16(d, gA1 + (size_t)arow * C_ + k0 + ac);
                cpa16(d + 32, gA1 + (size_t)arow * C_ + k0 + ac + 16);
            }
            d = s2u(base + 2 * A_TILE + brow * APAD + bc);
            cpa16(d, gB0 + (size_t)brow * C_ + k0 + bc);
            d = s2u(base + 2 * A_TILE + B_TILE + brow * APAD + bc);
            cpa16(d, gB1 + (size_t)brow * C_ + k0 + bc);
        }
        asm volatile("cp.async.commit_group;");

        const __half* As0 = sm + s * STAGE_H;
        const __half* As1 = As0 + A_TILE;
        const __half* Bs0 = As0 + 2 * A_TILE;
        const __half* Bs1 = Bs0 + B_TILE;
#pragma unroll
        for (int j = 0; j < 2; j++) {            // two k16 per BK=32
            uint32_t b0f[4][2], b1f[4][2];
            {
                int col = j * 16 + colB4base;
#pragma unroll
                for (int nt2 = 0; nt2 < 2; nt2++) {
                    uint32_t t4[4];
                    ldmx4(t4, s2u(Bs0 + (rB4 + nt2 * 16) * APAD + col));
                    b0f[nt2 * 2][0] = t4[0]; b0f[nt2 * 2][1] = t4[1];
                    b0f[nt2 * 2 + 1][0] = t4[2]; b0f[nt2 * 2 + 1][1] = t4[3];
                    ldmx4(t4, s2u(Bs1 + (rB4 + nt2 * 16) * APAD + col));
                    b1f[nt2 * 2][0] = t4[0]; b1f[nt2 * 2][1] = t4[1];
                    b1f[nt2 * 2 + 1][0] = t4[2]; b1f[nt2 * 2 + 1][1] = t4[3];
                }
            }
#pragma unroll
            for (int mt = 0; mt < 2; mt++) {
                int r = warp_m * 32 + mt * 16 + (lane & 15);
                int col = j * 16 + (lane >> 4) * 8;
                uint32_t a0f[4], a1f[4];
                ldmx4(a0f, s2u(As0 + r * APAD + col));
                if (doA1) ldmx4(a1f, s2u(As1 + r * APAD + col));
#pragma unroll
                for (int nt = 0; nt < 4; nt++) mma16816(acc[mt][nt], a0f, b0f[nt]);
#pragma unroll
                for (int nt = 0; nt < 4; nt++) mma16816(acc[mt][nt], a0f, b1f[nt]);
                if (doA1) {
#pragma unroll
                    for (int nt = 0; nt < 4; nt++) mma16816(acc[mt][nt], a1f, b0f[nt]);
                }
            }
        }
    }

    // epilogue: gmem writes + bias + fused BN column statistics
#pragma unroll
    for (int nt = 0; nt < 4; nt++) {
        int cc = n0 + warp_n * 32 + nt * 8 + (lane & 3) * 2;
        float b0v = bias[cc], b1v = bias[cc + 1];
        double s0 = 0.0, s1 = 0.0, q0 = 0.0, q1 = 0.0;
#pragma unroll
        for (int mt = 0; mt < 2; mt++) {
            int rr = m0 + warp_m * 32 + mt * 16 + (lane >> 2);
            float v00 = acc[mt][nt][0] + b0v;
            float v01 = acc[mt][nt][1] + b1v;
            float v10 = acc[mt][nt][2] + b0v;
            float v11 = acc[mt][nt][3] + b1v;
            float* y0 = Y + (size_t)rr * C_ + cc;
            y0[0] = v00; y0[1] = v01;
            float* y1 = Y + (size_t)(rr + 8) * C_ + cc;
            y1[0] = v10; y1[1] = v11;
            s0 += (double)v00 + (double)v10;
            s1 += (double)v01 + (double)v11;
            q0 += (double)v00 * (double)v00 + (double)v10 * (double)v10;
            q1 += (double)v01 * (double)v01 + (double)v11 * (double)v11;
        }
#pragma unroll
        for (int off = 4; off < 32; off <<= 1) {
            s0 += __shfl_xor_sync(0xffffffffu, s0, off);
            s1 += __shfl_xor_sync(0xffffffffu, s1, off);
            q0 += __shfl_xor_sync(0xffffffffu, q0, off);
            q1 += __shfl_xor_sync(0xffffffffu, q1, off);
        }
        if (lane < 4) {
            atomicAdd(&g_sum[slot * C_ + cc], s0);
            atomicAdd(&g_sum[slot * C_ + cc + 1], s1);
            atomicAdd(&g_sumsq[slot * C_ + cc], q0);
            atomicAdd(&g_sumsq[slot * C_ + cc + 1], q1);
        }
    }
}

// ---------------- fp32 -> 2x fp16 split (Dekker) ----------------
__global__ void split2_k(const float* __restrict__ in, size_t n,
                         __half* __restrict__ o0, __half* __restrict__ o1)
{
    size_t i = (size_t)blockIdx.x * blockDim.x + threadIdx.x;
    if (i >= n) return;
    float x = in[i];
    __half h0 = __float2half_rn(x);
    float r1 = __fsub_rn(x, __half2float(h0));
    o0[i] = h0; o1[i] = __float2half_rn(r1);
}

// split q,k,v weights in one launch
#define SPLITW_BLOCKS ((int)((3 * WELEMS + 511) / 512))
__global__ void splitW3_k(P3f w, __half* __restrict__ o0, __half* __restrict__ o1)
{
    size_t i = (size_t)blockIdx.x * blockDim.x + threadIdx.x;
    if (i >= 3 * WELEMS) return;
    int branch = (int)(i / WELEMS);
    size_t off = i - (size_t)branch * WELEMS;
    float x = w.p[branch][off];
    __half h0 = __float2half_rn(x);
    float r1 = __fsub_rn(x, __half2float(h0));
    o0[i] = h0; o1[i] = __float2half_rn(r1);
}

// ---------------- zero stat slots (tiny; keeps GEMM at launch index 3) ----------------
__global__ void zero_stats() {
    int c = threadIdx.x;
#pragma unroll
    for (int s = 0; s < 4; s++) {
        g_sum[s * C_ + c] = 0.0;
        g_sumsq[s * C_ + c] = 0.0;
    }
}

// ---------------- BN finalize: fp64 sums -> float mean/rstd (tiny) ----------------
__global__ void bn_fin(int slotbase, int nslots) {
    int i = blockIdx.x * blockDim.x + threadIdx.x;
    if (i >= nslots * C_) return;
    int slot = slotbase + i / C_;
    int c = i % C_;
    double m = g_sum[slot * C_ + c] * (1.0 / (double)M_);
    double var = g_sumsq[slot * C_ + c] * (1.0 / (double)M_) - m * m;
    float vf = (float)var;
    g_meanf[slot * C_ + c] = (float)m;
    g_rstdf[slot * C_ + c] = (float)(1.0 / sqrt((double)(vf + 1e-5f)));
}

// ---------------- BN + LIF (tau=2, v_th=1) + bit-pack, 3 branches, 8 bn/block ----------------
#define BN_PER_BLK 8
__global__ __launch_bounds__(512) void bn_lif_pack3(
    const float* __restrict__ ybase, P3f gamma, P3f beta, P3u bits)
{
    int c = threadIdx.x;
    int branch = blockIdx.y;
    const float* y = ybase + (size_t)branch * ELEMS;
    float mean = g_meanf[branch * C_ + c], r = g_rstdf[branch * C_ + c];
    float g = gamma.p[branch][c], be = beta.p[branch][c];
    unsigned int* bb = bits.p[branch];
    int h = c >> 6, lane = c & 31, half = (c >> 5) & 1;
    int bn0 = blockIdx.x * BN_PER_BLK;
#pragma unroll
    for (int i = 0; i < BN_PER_BLK; i++) {
        int bn = bn0 + i;
        int b = bn / N_, n = bn % N_;
        float x0 = y[((size_t)0 * (B_ * N_) + bn) * C_ + c];
        float x1 = y[((size_t)1 * (B_ * N_) + bn) * C_ + c];
        float x2 = y[((size_t)2 * (B_ * N_) + bn) * C_ + c];
        float x3 = y[((size_t)3 * (B_ * N_) + bn) * C_ + c];
        float xs[4] = {x0, x1, x2, x3};
        float v = 0.f;
#pragma unroll
        for (int t = 0; t < T_; t++) {
            float xb = __fadd_rn(__fmul_rn(__fmul_rn(__fsub_rn(xs[t], mean), r), g), be);
            v = __fadd_rn(v, __fmul_rn(__fsub_rn(xb, v), 0.5f));
            unsigned sp = (v >= 1.0f) ? 1u : 0u;
            if (sp) v = 0.f;
            unsigned bal = __ballot_sync(0xffffffffu, sp);
            if (lane == 0)
                bb[((size_t)((t * B_ + b) * H_ + h) * N_ + n) * 2 + half] = bal;
        }
    }
}

// ---------------- Attention: exact integer math; writes uint16 accumulators ----------------
__global__ __launch_bounds__(256) void attn_kernel(
    const float* __restrict__ policy,
    const unsigned int* __restrict__ qbi, const unsigned int* __restrict__ kbi,
    const unsigned int* __restrict__ vbi, unsigned short* __restrict__ out)
{
    __shared__ uint2 qs[N_];
    __shared__ uint2 ks[N_];
    __shared__ int vT[HD][53];
    __shared__ int srow[8][53];
    __shared__ unsigned char keep[N_];

    int blk = blockIdx.x;
    int h = blk % H_;
    int tb = blk / H_;
    int tid = threadIdx.x;

    const uint2* qp = (const uint2*)qbi + (size_t)(tb * H_ + h) * N_;
    const uint2* kp = (const uint2*)kbi + (size_t)(tb * H_ + h) * N_;
    for (int i = tid; i < N_; i += 256) {
        qs[i] = qp[i];
        ks[i] = kp[i];
        keep[i] = (policy[(size_t)tb * N_ + i] != 0.0f) ? 1 : 0;
    }
    const unsigned int* vp = vbi + (size_t)(tb * H_ + h) * N_ * 2;
    for (int i = tid; i < N_ * 2; i += 256) {
        unsigned w = vp[i];
        int m = i >> 1, dbase = (i & 1) * 32;
#pragma unroll
        for (int j = 0; j < 32; j++)
            ((unsigned char*)vT[dbase + j])[m] = (unsigned char)((w >> j) & 1u);
    }
    __syncthreads();

    int warp = tid >> 5, lane = tid & 31;
    for (int n = warp; n < N_; n += 8) {
        uint2 q = qs[n];
        for (int m = lane; m < 212; m += 32) {
            int s = 0;
            if (m < N_) {
                uint2 kk = ks[m];
                s = __popc(q.x & kk.x) + __popc(q.y & kk.y);
                if (!(keep[m] || (m == n))) s = 0;
            }
            ((unsigned char*)srow[warp])[m] = (unsigned char)s;
        }
        __syncwarp();
        int acc0 = 0, acc1 = 0;
#pragma unroll
        for (int q4 = 0; q4 < 53; q4++) {
            int sv = srow[warp][q4];
            acc0 = __dp4a(sv, vT[lane][q4], acc0);
            acc1 = __dp4a(sv, vT[lane + 32][q4], acc1);
        }
        unsigned short* op = out + ((size_t)tb * N_ + n) * C_ + h * HD;
        op[lane]      = (unsigned short)acc0;
        op[lane + 32] = (unsigned short)acc1;
        __syncwarp();
    }
}

// ---------------- attn LIF (v_th=0.5): uint16 acc -> fp16 spikes (exact) ----------------
__global__ void lif_attn(const unsigned short* __restrict__ in,
                         __half* __restrict__ outs) {
    size_t idx = (size_t)blockIdx.x * blockDim.x + threadIdx.x;
    if (idx >= BNC) return;
    float v = 0.f;
    const __half one = __float2half(1.0f);
    const __half zero = __float2half(0.0f);
    unsigned short a0 = in[(size_t)0 * BNC + idx];
    unsigned short a1 = in[(size_t)1 * BNC + idx];
    unsigned short a2 = in[(size_t)2 * BNC + idx];
    unsigned short a3 = in[(size_t)3 * BNC + idx];
    float xs[4] = {(float)a0 * 0.125f, (float)a1 * 0.125f,
                   (float)a2 * 0.125f, (float)a3 * 0.125f};
#pragma unroll
    for (int t = 0; t < T_; t++) {
        v = __fadd_rn(v, __fmul_rn(__fsub_rn(xs[t], v), 0.5f));
        unsigned sp = (v >= 0.5f) ? 1u : 0u;
        outs[(size_t)t * BNC + idx] = sp ? one : zero;
        if (sp) v = 0.f;
    }
}

// ---------------- final BN + LIF writing fp32 spikes (slot 3), float4 vectorized ---------
__global__ __launch_bounds__(512) void bn_lif_out(
    const float* __restrict__ y, const float* __restrict__ gamma,
    const float* __restrict__ beta, float* __restrict__ out)
{
    int c4 = (threadIdx.x & 127) * 4;
    int bsub = threadIdx.x >> 7;            // 0..3
    float4 mean = *(const float4*)&g_meanf[3 * C_ + c4];
    float4 rst  = *(const float4*)&g_rstdf[3 * C_ + c4];
    float4 gm   = *(const float4*)&gamma[c4];
    float4 bt   = *(const float4*)&beta[c4];
#pragma unroll
    for (int pass = 0; pass < 2; pass++) {
        int bn = blockIdx.x * BN_PER_BLK + pass * 4 + bsub;
        float4 xs[4];
#pragma unroll
        for (int t = 0; t < T_; t++)
            xs[t] = *(const float4*)&y[((size_t)t * (B_ * N_) + bn) * C_ + c4];
        float v0 = 0.f, v1 = 0.f, v2 = 0.f, v3 = 0.f;
#pragma unroll
        for (int t = 0; t < T_; t++) {
            float xb0 = __fadd_rn(__fmul_rn(__fmul_rn(__fsub_rn(xs[t].x, mean.x), rst.x), gm.x), bt.x);
            float xb1 = __fadd_rn(__fmul_rn(__fmul_rn(__fsub_rn(xs[t].y, mean.y), rst.y), gm.y), bt.y);
            float xb2 = __fadd_rn(__fmul_rn(__fmul_rn(__fsub_rn(xs[t].z, mean.z), rst.z), gm.z), bt.z);
            float xb3 = __fadd_rn(__fmul_rn(__fmul_rn(__fsub_rn(xs[t].w, mean.w), rst.w), gm.w), bt.w);
            v0 = __fadd_rn(v0, __fmul_rn(__fsub_rn(xb0, v0), 0.5f));
            v1 = __fadd_rn(v1, __fmul_rn(__fsub_rn(xb1, v1), 0.5f));
            v2 = __fadd_rn(v2, __fmul_rn(__fsub_rn(xb2, v2), 0.5f));
            v3 = __fadd_rn(v3, __fmul_rn(__fsub_rn(xb3, v3), 0.5f));
            float4 o;
            o.x = (v0 >= 1.0f) ? 1.0f : 0.0f;
            o.y = (v1 >= 1.0f) ? 1.0f : 0.0f;
            o.z = (v2 >= 1.0f) ? 1.0f : 0.0f;
            o.w = (v3 >= 1.0f) ? 1.0f : 0.0f;
            if (o.x != 0.f) v0 = 0.f;
            if (o.y != 0.f) v1 = 0.f;
            if (o.z != 0.f) v2 = 0.f;
            if (o.w != 0.f) v3 = 0.f;
            *(float4*)&out[((size_t)t * (B_ * N_) + bn) * C_ + c4] = o;
        }
    }
}

// ---------------- launch ----------------
extern "C" void kernel_launch(void* const* d_in, const int* in_sizes, int n_in,
                              void* d_out, int out_size)
{
    const float* x      = (const float*)d_in[0];
    const float* policy = (const float*)d_in[1];
    const float* qw  = (const float*)d_in[2];
    const float* qb  = (const float*)d_in[3];
    const float* qg  = (const float*)d_in[4];
    const float* qbe = (const float*)d_in[5];
    const float* kw  = (const float*)d_in[6];
    const float* kb  = (const float*)d_in[7];
    const float* kg  = (const float*)d_in[8];
    const float* kbe = (const float*)d_in[9];
    const float* vw  = (const float*)d_in[10];
    const float* vb  = (const float*)d_in[11];
    const float* vg  = (const float*)d_in[12];
    const float* vbe = (const float*)d_in[13];
    const float* pw  = (const float*)d_in[14];
    const float* pb  = (const float*)d_in[15];
    const float* pg  = (const float*)d_in[16];
    const float* pbe = (const float*)d_in[17];
    float* out = (float*)d_out;

    float *Y;
    unsigned short *AT16;
    __half *X0, *X1, *PA, *W0, *W1;
    unsigned int *QB, *KB, *VB;
    cudaGetSymbolAddress((void**)&Y,  g_y);
    cudaGetSymbolAddress((void**)&AT16, g_attn16);
    cudaGetSymbolAddress((void**)&X0, g_x0);
    cudaGetSymbolAddress((void**)&X1, g_x1);
    cudaGetSymbolAddress((void**)&PA, g_pA);
    cudaGetSymbolAddress((void**)&W0, g_w0);
    cudaGetSymbolAddress((void**)&W1, g_w1);
    cudaGetSymbolAddress((void**)&QB, g_qbits);
    cudaGetSymbolAddress((void**)&KB, g_kbits);
    cudaGetSymbolAddress((void**)&VB, g_vbits);

    cudaFuncSetAttribute(gemm_fp16_mma, cudaFuncAttributeMaxDynamicSharedMemorySize,
                         (int)GSMEM);

    // 0. split x
    split2_k<<<(int)((ELEMS + 511) / 512), 512>>>(x, ELEMS, X0, X1);
    // 1. split q,k,v weights
    P3f wP; wP.p[0] = qw; wP.p[1] = kw; wP.p[2] = vw;
    splitW3_k<<<SPLITW_BLOCKS, 512>>>(wP, W0, W1);
    // 2. zero stat slots (tiny; keeps GEMM at profiled launch slot 3)
    zero_stats<<<1, C_>>>();
    // 3. fused q/k/v GEMM with fused BN stats (slots 0..2)  <-- profiled
    P3f biasP; biasP.p[0] = qb; biasP.p[1] = kb; biasP.p[2] = vb;
    gemm_fp16_mma<<<dim3(24, M_ / 128), 256, GSMEM>>>(X0, X1, W0, W1, biasP, Y, 1, 0);
    // 4. BN finalize (slots 0..2)
    bn_fin<<<(3 * C_ + 255) / 256, 256>>>(0, 3);
    // 5. BN + LIF + pack (3 branches, 8 bn/block)
    P3f gP; gP.p[0] = qg; gP.p[1] = kg; gP.p[2] = vg;
    P3f beP; beP.p[0] = qbe; beP.p[1] = kbe; beP.p[2] = vbe;
    P3u bitsP; bitsP.p[0] = QB; bitsP.p[1] = KB; bitsP.p[2] = VB;
    bn_lif_pack3<<<dim3(B_ * N_ / BN_PER_BLK, 3), 512>>>(Y, gP, beP, bitsP);
    // 6-7. attention (uint16) + attn LIF
    attn_kernel<<<T_ * B_ * H_, 256>>>(policy, QB, KB, VB, AT16);
    lif_attn<<<(int)((BNC + 255) / 256), 256>>>(AT16, PA);
    // 8. split proj weights
    split2_k<<<(int)((WELEMS + 511) / 512), 512>>>(pw, WELEMS, W0, W1);
    // 9. projection GEMM with fused BN stats (slot 3)
    P3f biasPp; biasPp.p[0] = pb; biasPp.p[1] = pb; biasPp.p[2] = pb;
    gemm_fp16_mma<<<dim3(8, M_ / 128), 256, GSMEM>>>(PA, PA, W0, W1, biasPp, Y, 0, 3);
    // 10. BN finalize (slot 3)
    bn_fin<<<2, 256>>>(3, 1);
    // 11. final BN + LIF (float4 vectorized)
    bn_lif_out<<<B_ * N_ / BN_PER_BLK, 512>>>(Y, pg, pbe, out);
}

// round 17
// speedup vs baseline: 1.1340x; 1.1340x over previous
#include <cuda_runtime.h>
#include <cuda_fp16.h>
#include <cstdint>
#include <math.h>

#define T_  4
#define B_  32
#define N_  196
#define C_  512
#define H_  8
#define HD  64
#define M_  (T_*B_*N_)          // 25088
#define ELEMS ((size_t)M_*C_)   // 12,845,056
#define BNC ((size_t)B_*N_*C_)
#define WELEMS ((size_t)C_*C_)

struct P3f { const float* p[3]; };
struct P3u { unsigned int* p[3]; };

// ---------------- scratch (device globals) ----------------
__device__ float g_y[3*ELEMS];                  // q,k,v GEMM outputs (proj reuses slot 0)
__device__ unsigned short g_attn16[ELEMS];      // attention integer accumulators (exact)
__device__ __half g_x0[ELEMS], g_x1[ELEMS];     // x fp16 splits
__device__ __half g_pA[ELEMS];                  // attn spikes (fp16, exact 0/1)
__device__ __half g_w0[3*WELEMS], g_w1[3*WELEMS];  // weight fp16 splits
__device__ unsigned int g_qbits[(size_t)T_*B_*H_*N_*2];
__device__ unsigned int g_kbits[(size_t)T_*B_*H_*N_*2];
__device__ unsigned int g_vbits[(size_t)T_*B_*H_*N_*2];
__device__ double g_sum[4*C_];
__device__ double g_sumsq[4*C_];

// ---------------- helpers ----------------
static __device__ __forceinline__ uint32_t s2u(const void* p) {
    uint32_t a;
    asm("{ .reg .u64 t; cvta.to.shared.u64 t, %1; cvt.u32.u64 %0, t; }" : "=r"(a) : "l"(p));
    return a;
}
static __device__ __forceinline__ void cpa16(uint32_t dst, const void* src) {
    asm volatile("cp.async.cg.shared.global [%0], [%1], 16;" :: "r"(dst), "l"(src));
}
static __device__ __forceinline__ void ldmx4(uint32_t* r, uint32_t addr) {
    asm volatile("ldmatrix.sync.aligned.m8n8.x4.shared.b16 {%0,%1,%2,%3}, [%4];"
                 : "=r"(r[0]), "=r"(r[1]), "=r"(r[2]), "=r"(r[3]) : "r"(addr));
}
static __device__ __forceinline__ void mma16816(float* c, const uint32_t* a,
                                                const uint32_t* b) {
    asm volatile(
        "mma.sync.aligned.m16n8k16.row.col.f32.f16.f16.f32 "
        "{%0,%1,%2,%3}, {%4,%5,%6,%7}, {%8,%9}, {%0,%1,%2,%3};"
        : "+f"(c[0]), "+f"(c[1]), "+f"(c[2]), "+f"(c[3])
        : "r"(a[0]), "r"(a[1]), "r"(a[2]), "r"(a[3]), "r"(b[0]), "r"(b[1]));
}
// BN params identical to former bn_fin arithmetic (bitwise-same results)
static __device__ __forceinline__ void bn_params(int slot, int c, float& mean,
                                                 float& rstd) {
    double m = g_sum[slot * C_ + c] * (1.0 / (double)M_);
    double var = g_sumsq[slot * C_ + c] * (1.0 / (double)M_) - m * m;
    float vf = (float)var;
    mean = (float)m;
    rstd = (float)(1.0 / sqrt((double)(vf + 1e-5f)));
}

// ---------------- fp16 split-GEMM on mma.sync (R15-proven config, frozen) ----------------
// Y[branch][M,512] = A0@B0^T + A0@B1^T + (doA1? A1@B0^T) + bias[branch]
// 128x128 tile, BK=32, 256 thr, 8 warps (2m x 4n), cp.async double buffer,
// phase-staggered k start, B-ldmx4, fused BN statistics epilogue.
#define APAD 40          // halfs per smem row (80 B)
#define TILE_H (128*APAD)
#define GSMEM (2*4*(size_t)TILE_H*sizeof(__half))   // 81920 B

__global__ __launch_bounds__(256) void gemm_fp16_mma(
    const __half* __restrict__ A0, const __half* __restrict__ A1,
    const __half* __restrict__ W0b, const __half* __restrict__ W1b,
    P3f biasP, float* __restrict__ Yb, int doA1, int slotbase)
{
    extern __shared__ __half sm[];
    const int tid = threadIdx.x;
    const int wid = tid >> 5, lane = tid & 31;
    const int bx = blockIdx.x;
    const int branch = bx >> 2;
    const int m0 = blockIdx.y * 128, n0 = (bx & 3) * 128;
    const int warp_m = wid & 1, warp_n = wid >> 1;
    const float* bias = biasP.p[branch];
    float* Y = Yb + (size_t)branch * ELEMS;
    const int slot = slotbase + branch;
    const int phase = ((bx + blockIdx.y) & 1) * 8;

    const __half* gsrc[4] = {A0 + (size_t)m0 * C_, A1 + (size_t)m0 * C_,
                             W0b + (size_t)branch * WELEMS + (size_t)n0 * C_,
                             W1b + (size_t)branch * WELEMS + (size_t)n0 * C_};
    const int row = tid >> 1;
    const int cb = (tid & 1) * 2;

#pragma unroll
    for (int o = 0; o < 4; o++) {
        if (o == 1 && !doA1) continue;
        uint32_t dst = s2u(sm + (size_t)o * TILE_H + row * APAD + cb * 8);
        const __half* src = gsrc[o] + (size_t)row * C_ + phase * 32 + cb * 8;
        cpa16(dst, src);
        cpa16(dst + 16, src + 8);
    }
    asm volatile("cp.async.commit_group;");

    float acc[4][4][4];
#pragma unroll
    for (int i = 0; i < 4; i++)
#pragma unroll
        for (int j = 0; j < 4; j++)
#pragma unroll
            for (int k = 0; k < 4; k++) acc[i][j][k] = 0.f;

    const int rB4 = warp_n * 32 + ((lane >> 4) << 3) + (lane & 7);
    const int colB4base = (((lane >> 3) & 1) << 3);

    for (int kcc = 0; kcc < 16; kcc++) {
        asm volatile("cp.async.wait_group 0;");
        __syncthreads();
        const int s = kcc & 1;
        if (kcc + 1 < 16) {
            int k0n = ((kcc + 1 + phase) & 15) * 32;
#pragma unroll
            for (int o = 0; o < 4; o++) {
                if (o == 1 && !doA1) continue;
                uint32_t dst = s2u(sm + (size_t)((s ^ 1) * 4 + o) * TILE_H +
                                   row * APAD + cb * 8);
                const __half* src = gsrc[o] + (size_t)row * C_ + k0n + cb * 8;
                cpa16(dst, src);
                cpa16(dst + 16, src + 8);
            }
            asm volatile("cp.async.commit_group;");
        }
        const __half* As0 = sm + (size_t)(s * 4 + 0) * TILE_H;
        const __half* As1 = sm + (size_t)(s * 4 + 1) * TILE_H;
        const __half* Bs0 = sm + (size_t)(s * 4 + 2) * TILE_H;
        const __half* Bs1 = sm + (size_t)(s * 4 + 3) * TILE_H;
#pragma unroll
        for (int j = 0; j < 2; j++) {
            uint32_t b0f[4][2], b1f[4][2];
            {
                int col = j * 16 + colB4base;
#pragma unroll
                for (int nt2 = 0; nt2 < 2; nt2++) {
                    uint32_t t4[4];
                    ldmx4(t4, s2u(Bs0 + (rB4 + nt2 * 16) * APAD + col));
                    b0f[nt2 * 2][0] = t4[0]; b0f[nt2 * 2][1] = t4[1];
                    b0f[nt2 * 2 + 1][0] = t4[2]; b0f[nt2 * 2 + 1][1] = t4[3];
                    ldmx4(t4, s2u(Bs1 + (rB4 + nt2 * 16) * APAD + col));
                    b1f[nt2 * 2][0] = t4[0]; b1f[nt2 * 2][1] = t4[1];
                    b1f[nt2 * 2 + 1][0] = t4[2]; b1f[nt2 * 2 + 1][1] = t4[3];
                }
            }
#pragma unroll
            for (int mt = 0; mt < 4; mt++) {
                int r = warp_m * 64 + mt * 16 + (lane & 15);
                int col = j * 16 + (lane >> 4) * 8;
                uint32_t a0f[4], a1f[4];
                ldmx4(a0f, s2u(As0 + r * APAD + col));
                if (doA1) ldmx4(a1f, s2u(As1 + r * APAD + col));
#pragma unroll
                for (int nt = 0; nt < 4; nt++) mma16816(acc[mt][nt], a0f, b0f[nt]);
#pragma unroll
                for (int nt = 0; nt < 4; nt++) mma16816(acc[mt][nt], a0f, b1f[nt]);
                if (doA1) {
#pragma unroll
                    for (int nt = 0; nt < 4; nt++) mma16816(acc[mt][nt], a1f, b0f[nt]);
                }
            }
        }
    }

    // epilogue: gmem writes + bias + fused BN column statistics
#pragma unroll
    for (int nt = 0; nt < 4; nt++) {
        int cc = n0 + warp_n * 32 + nt * 8 + (lane & 3) * 2;
        float b0v = bias[cc], b1v = bias[cc + 1];
        double s0 = 0.0, s1 = 0.0, q0 = 0.0, q1 = 0.0;
#pragma unroll
        for (int mt = 0; mt < 4; mt++) {
            int rr = m0 + warp_m * 64 + mt * 16 + (lane >> 2);
            float v00 = acc[mt][nt][0] + b0v;
            float v01 = acc[mt][nt][1] + b1v;
            float v10 = acc[mt][nt][2] + b0v;
            float v11 = acc[mt][nt][3] + b1v;
            float* y0 = Y + (size_t)rr * C_ + cc;
            y0[0] = v00; y0[1] = v01;
            float* y1 = Y + (size_t)(rr + 8) * C_ + cc;
            y1[0] = v10; y1[1] = v11;
            s0 += (double)v00 + (double)v10;
            s1 += (double)v01 + (double)v11;
            q0 += (double)v00 * (double)v00 + (double)v10 * (double)v10;
            q1 += (double)v01 * (double)v01 + (double)v11 * (double)v11;
        }
#pragma unroll
        for (int off = 4; off < 32; off <<= 1) {
            s0 += __shfl_xor_sync(0xffffffffu, s0, off);
            s1 += __shfl_xor_sync(0xffffffffu, s1, off);
            q0 += __shfl_xor_sync(0xffffffffu, q0, off);
            q1 += __shfl_xor_sync(0xffffffffu, q1, off);
        }
        if (lane < 4) {
            atomicAdd(&g_sum[slot * C_ + cc], s0);
            atomicAdd(&g_sum[slot * C_ + cc + 1], s1);
            atomicAdd(&g_sumsq[slot * C_ + cc], q0);
            atomicAdd(&g_sumsq[slot * C_ + cc + 1], q1);
        }
    }
}

// ---------------- fp32 -> 2x fp16 split, vectorized 4/thread ----------------
__global__ void split2_k(const float* __restrict__ in, size_t n4,
                         __half* __restrict__ o0, __half* __restrict__ o1)
{
    size_t i = (size_t)blockIdx.x * blockDim.x + threadIdx.x;
    if (i >= n4) return;
    float4 x = ((const float4*)in)[i];
    __half2 h0a, h0b, h1a, h1b;
    {
        __half a = __float2half_rn(x.x), b = __float2half_rn(x.y);
        h0a = __halves2half2(a, b);
        h1a = __halves2half2(__float2half_rn(__fsub_rn(x.x, __half2float(a))),
                             __float2half_rn(__fsub_rn(x.y, __half2float(b))));
        __half c = __float2half_rn(x.z), d = __float2half_rn(x.w);
        h0b = __halves2half2(c, d);
        h1b = __halves2half2(__float2half_rn(__fsub_rn(x.z, __half2float(c))),
                             __float2half_rn(__fsub_rn(x.w, __half2float(d))));
    }
    ((__half2*)o0)[i * 2] = h0a; ((__half2*)o0)[i * 2 + 1] = h0b;
    ((__half2*)o1)[i * 2] = h1a; ((__half2*)o1)[i * 2 + 1] = h1b;
}

// split q,k,v weights (vectorized) + zero stat slots in a dedicated extra block
#define SPLITW_BLOCKS ((int)((3 * WELEMS / 4 + 255) / 256))
__global__ void splitW3_k(P3f w, __half* __restrict__ o0, __half* __restrict__ o1)
{
    if (blockIdx.x == SPLITW_BLOCKS) {
        if (threadIdx.x < 256) {
#pragma unroll
            for (int s = 0; s < 8; s++) {
                g_sum[s * 256 + threadIdx.x] = 0.0;
                g_sumsq[s * 256 + threadIdx.x] = 0.0;
            }
        }
        return;
    }
    size_t i = (size_t)blockIdx.x * blockDim.x + threadIdx.x;
    if (i >= 3 * WELEMS / 4) return;
    int branch = (int)(i / (WELEMS / 4));
    size_t off = i - (size_t)branch * (WELEMS / 4);
    float4 x = ((const float4*)w.p[branch])[off];
    __half a = __float2half_rn(x.x), b = __float2half_rn(x.y);
    __half c = __float2half_rn(x.z), d = __float2half_rn(x.w);
    __half2 h0a = __halves2half2(a, b), h0b = __halves2half2(c, d);
    __half2 h1a = __halves2half2(__float2half_rn(__fsub_rn(x.x, __half2float(a))),
                                 __float2half_rn(__fsub_rn(x.y, __half2float(b))));
    __half2 h1b = __halves2half2(__float2half_rn(__fsub_rn(x.z, __half2float(c))),
                                 __float2half_rn(__fsub_rn(x.w, __half2float(d))));
    ((__half2*)o0)[i * 2] = h0a; ((__half2*)o0)[i * 2 + 1] = h0b;
    ((__half2*)o1)[i * 2] = h1a; ((__half2*)o1)[i * 2 + 1] = h1b;
}

// ---------------- BN + LIF (tau=2, v_th=1) + bit-pack, 3 branches, 8 bn/block ----------------
#define BN_PER_BLK 8
__global__ __launch_bounds__(512) void bn_lif_pack3(
    const float* __restrict__ ybase, P3f gamma, P3f beta, P3u bits)
{
    int c = threadIdx.x;
    int branch = blockIdx.y;
    const float* y = ybase + (size_t)branch * ELEMS;
    float mean, r;
    bn_params(branch, c, mean, r);
    float g = gamma.p[branch][c], be = beta.p[branch][c];
    unsigned int* bb = bits.p[branch];
    int h = c >> 6, lane = c & 31, half = (c >> 5) & 1;
    int bn0 = blockIdx.x * BN_PER_BLK;
#pragma unroll
    for (int i = 0; i < BN_PER_BLK; i++) {
        int bn = bn0 + i;
        int b = bn / N_, n = bn % N_;
        float x0 = y[((size_t)0 * (B_ * N_) + bn) * C_ + c];
        float x1 = y[((size_t)1 * (B_ * N_) + bn) * C_ + c];
        float x2 = y[((size_t)2 * (B_ * N_) + bn) * C_ + c];
        float x3 = y[((size_t)3 * (B_ * N_) + bn) * C_ + c];
        float xs[4] = {x0, x1, x2, x3};
        float v = 0.f;
#pragma unroll
        for (int t = 0; t < T_; t++) {
            float xb = __fadd_rn(__fmul_rn(__fmul_rn(__fsub_rn(xs[t], mean), r), g), be);
            v = __fadd_rn(v, __fmul_rn(__fsub_rn(xb, v), 0.5f));
            unsigned sp = (v >= 1.0f) ? 1u : 0u;
            if (sp) v = 0.f;
            unsigned bal = __ballot_sync(0xffffffffu, sp);
            if (lane == 0)
                bb[((size_t)((t * B_ + b) * H_ + h) * N_ + n) * 2 + half] = bal;
        }
    }
}

// ---------------- Attention: exact integer math; writes uint16 accumulators ----------------
__global__ __launch_bounds__(256) void attn_kernel(
    const float* __restrict__ policy,
    const unsigned int* __restrict__ qbi, const unsigned int* __restrict__ kbi,
    const unsigned int* __restrict__ vbi, unsigned short* __restrict__ out)
{
    __shared__ uint2 qs[N_];
    __shared__ uint2 ks[N_];
    __shared__ int vT[HD][53];
    __shared__ int srow[8][53];
    __shared__ unsigned char keep[N_];

    int blk = blockIdx.x;
    int h = blk % H_;
    int tb = blk / H_;
    int tid = threadIdx.x;

    const uint2* qp = (const uint2*)qbi + (size_t)(tb * H_ + h) * N_;
    const uint2* kp = (const uint2*)kbi + (size_t)(tb * H_ + h) * N_;
    for (int i = tid; i < N_; i += 256) {
        qs[i] = qp[i];
        ks[i] = kp[i];
        keep[i] = (policy[(size_t)tb * N_ + i] != 0.0f) ? 1 : 0;
    }
    const unsigned int* vp = vbi + (size_t)(tb * H_ + h) * N_ * 2;
    for (int i = tid; i < N_ * 2; i += 256) {
        unsigned w = vp[i];
        int m = i >> 1, dbase = (i & 1) * 32;
#pragma unroll
        for (int j = 0; j < 32; j++)
            ((unsigned char*)vT[dbase + j])[m] = (unsigned char)((w >> j) & 1u);
    }
    __syncthreads();

    int warp = tid >> 5, lane = tid & 31;
    for (int n = warp; n < N_; n += 8) {
        uint2 q = qs[n];
        for (int m = lane; m < 212; m += 32) {
            int s = 0;
            if (m < N_) {
                uint2 kk = ks[m];
                s = __popc(q.x & kk.x) + __popc(q.y & kk.y);
                if (!(keep[m] || (m == n))) s = 0;
            }
            ((unsigned char*)srow[warp])[m] = (unsigned char)s;
        }
        __syncwarp();
        int acc0 = 0, acc1 = 0;
#pragma unroll
        for (int q4 = 0; q4 < 53; q4++) {
            int sv = srow[warp][q4];
            acc0 = __dp4a(sv, vT[lane][q4], acc0);
            acc1 = __dp4a(sv, vT[lane + 32][q4], acc1);
        }
        unsigned short* op = out + ((size_t)tb * N_ + n) * C_ + h * HD;
        op[lane]      = (unsigned short)acc0;
        op[lane + 32] = (unsigned short)acc1;
        __syncwarp();
    }
}

// ---------------- attn LIF (v_th=0.5): uint16 acc -> fp16 spikes (exact) ----------------
__global__ void lif_attn(const unsigned short* __restrict__ in,
                         __half* __restrict__ outs) {
    size_t idx = (size_t)blockIdx.x * blockDim.x + threadIdx.x;
    if (idx >= BNC) return;
    float v = 0.f;
    const __half one = __float2half(1.0f);
    const __half zero = __float2half(0.0f);
    unsigned short a0 = in[(size_t)0 * BNC + idx];
    unsigned short a1 = in[(size_t)1 * BNC + idx];
    unsigned short a2 = in[(size_t)2 * BNC + idx];
    unsigned short a3 = in[(size_t)3 * BNC + idx];
    float xs[4] = {(float)a0 * 0.125f, (float)a1 * 0.125f,
                   (float)a2 * 0.125f, (float)a3 * 0.125f};
#pragma unroll
    for (int t = 0; t < T_; t++) {
        v = __fadd_rn(v, __fmul_rn(__fsub_rn(xs[t], v), 0.5f));
        unsigned sp = (v >= 0.5f) ? 1u : 0u;
        outs[(size_t)t * BNC + idx] = sp ? one : zero;
        if (sp) v = 0.f;
    }
}

// ---------------- final BN + LIF writing fp32 spikes (slot 3), float4 vectorized ---------
__global__ __launch_bounds__(512) void bn_lif_out(
    const float* __restrict__ y, const float* __restrict__ gamma,
    const float* __restrict__ beta, float* __restrict__ out)
{
    int c4 = (threadIdx.x & 127) * 4;
    int bsub = threadIdx.x >> 7;            // 0..3
    float4 mean, rst;
    bn_params(3, c4 + 0, mean.x, rst.x);
    bn_params(3, c4 + 1, mean.y, rst.y);
    bn_params(3, c4 + 2, mean.z, rst.z);
    bn_params(3, c4 + 3, mean.w, rst.w);
    float4 gm   = *(const float4*)&gamma[c4];
    float4 bt   = *(const float4*)&beta[c4];
#pragma unroll
    for (int pass = 0; pass < 2; pass++) {
        int bn = blockIdx.x * BN_PER_BLK + pass * 4 + bsub;
        float4 xs[4];
#pragma unroll
        for (int t = 0; t < T_; t++)
            xs[t] = *(const float4*)&y[((size_t)t * (B_ * N_) + bn) * C_ + c4];
        float v0 = 0.f, v1 = 0.f, v2 = 0.f, v3 = 0.f;
#pragma unroll
        for (int t = 0; t < T_; t++) {
            float xb0 = __fadd_rn(__fmul_rn(__fmul_rn(__fsub_rn(xs[t].x, mean.x), rst.x), gm.x), bt.x);
            float xb1 = __fadd_rn(__fmul_rn(__fmul_rn(__fsub_rn(xs[t].y, mean.y), rst.y), gm.y), bt.y);
            float xb2 = __fadd_rn(__fmul_rn(__fmul_rn(__fsub_rn(xs[t].z, mean.z), rst.z), gm.z), bt.z);
            float xb3 = __fadd_rn(__fmul_rn(__fmul_rn(__fsub_rn(xs[t].w, mean.w), rst.w), gm.w), bt.w);
            v0 = __fadd_rn(v0, __fmul_rn(__fsub_rn(xb0, v0), 0.5f));
            v1 = __fadd_rn(v1, __fmul_rn(__fsub_rn(xb1, v1), 0.5f));
            v2 = __fadd_rn(v2, __fmul_rn(__fsub_rn(xb2, v2), 0.5f));
            v3 = __fadd_rn(v3, __fmul_rn(__fsub_rn(xb3, v3), 0.5f));
            float4 o;
            o.x = (v0 >= 1.0f) ? 1.0f : 0.0f;
            o.y = (v1 >= 1.0f) ? 1.0f : 0.0f;
            o.z = (v2 >= 1.0f) ? 1.0f : 0.0f;
            o.w = (v3 >= 1.0f) ? 1.0f : 0.0f;
            if (o.x != 0.f) v0 = 0.f;
            if (o.y != 0.f) v1 = 0.f;
            if (o.z != 0.f) v2 = 0.f;
            if (o.w != 0.f) v3 = 0.f;
            *(float4*)&out[((size_t)t * (B_ * N_) + bn) * C_ + c4] = o;
        }
    }
}

// ---------------- launch ----------------
extern "C" void kernel_launch(void* const* d_in, const int* in_sizes, int n_in,
                              void* d_out, int out_size)
{
    const float* x      = (const float*)d_in[0];
    const float* policy = (const float*)d_in[1];
    const float* qw  = (const float*)d_in[2];
    const float* qb  = (const float*)d_in[3];
    const float* qg  = (const float*)d_in[4];
    const float* qbe = (const float*)d_in[5];
    const float* kw  = (const float*)d_in[6];
    const float* kb  = (const float*)d_in[7];
    const float* kg  = (const float*)d_in[8];
    const float* kbe = (const float*)d_in[9];
    const float* vw  = (const float*)d_in[10];
    const float* vb  = (const float*)d_in[11];
    const float* vg  = (const float*)d_in[12];
    const float* vbe = (const float*)d_in[13];
    const float* pw  = (const float*)d_in[14];
    const float* pb  = (const float*)d_in[15];
    const float* pg  = (const float*)d_in[16];
    const float* pbe = (const float*)d_in[17];
    float* out = (float*)d_out;

    float *Y;
    unsigned short *AT16;
    __half *X0, *X1, *PA, *W0, *W1;
    unsigned int *QB, *KB, *VB;
    cudaGetSymbolAddress((void**)&Y,  g_y);
    cudaGetSymbolAddress((void**)&AT16, g_attn16);
    cudaGetSymbolAddress((void**)&X0, g_x0);
    cudaGetSymbolAddress((void**)&X1, g_x1);
    cudaGetSymbolAddress((void**)&PA, g_pA);
    cudaGetSymbolAddress((void**)&W0, g_w0);
    cudaGetSymbolAddress((void**)&W1, g_w1);
    cudaGetSymbolAddress((void**)&QB, g_qbits);
    cudaGetSymbolAddress((void**)&KB, g_kbits);
    cudaGetSymbolAddress((void**)&VB, g_vbits);

    cudaFuncSetAttribute(gemm_fp16_mma, cudaFuncAttributeMaxDynamicSharedMemorySize,
                         (int)GSMEM);

    // 0. split x (vectorized, 4/thread)
    split2_k<<<(int)((ELEMS / 4 + 255) / 256), 256>>>(x, ELEMS / 4, X0, X1);
    // 1. split q,k,v weights + zero stat slots
    P3f wP; wP.p[0] = qw; wP.p[1] = kw; wP.p[2] = vw;
    splitW3_k<<<SPLITW_BLOCKS + 1, 256>>>(wP, W0, W1);
    // 2. fused q/k/v GEMM with fused BN stats (slots 0..2)
    P3f biasP; biasP.p[0] = qb; biasP.p[1] = kb; biasP.p[2] = vb;
    gemm_fp16_mma<<<dim3(12, M_ / 128), 256, GSMEM>>>(X0, X1, W0, W1, biasP, Y, 1, 0);
    // 3. BN + LIF + pack (3 branches, 8 bn/block, inline stats finalize)
    P3f gP; gP.p[0] = qg; gP.p[1] = kg; gP.p[2] = vg;
    P3f beP; beP.p[0] = qbe; beP.p[1] = kbe; beP.p[2] = vbe;
    P3u bitsP; bitsP.p[0] = QB; bitsP.p[1] = KB; bitsP.p[2] = VB;
    bn_lif_pack3<<<dim3(B_ * N_ / BN_PER_BLK, 3), 512>>>(Y, gP, beP, bitsP);
    // 4-5. attention (uint16) + attn LIF
    attn_kernel<<<T_ * B_ * H_, 256>>>(policy, QB, KB, VB, AT16);
    lif_attn<<<(int)((BNC + 255) / 256), 256>>>(AT16, PA);
    // 6. split proj weights (vectorized)
    split2_k<<<(int)((WELEMS / 4 + 255) / 256), 256>>>(pw, WELEMS / 4, W0, W1);
    // 7. projection GEMM with fused BN stats (slot 3)
    P3f biasPp; biasPp.p[0] = pb; biasPp.p[1] = pb; biasPp.p[2] = pb;
    gemm_fp16_mma<<<dim3(4, M_ / 128), 256, GSMEM>>>(PA, PA, W0, W1, biasPp, Y, 0, 3);
    // 8. final BN + LIF (float4 vectorized, inline stats finalize)
    bn_lif_out<<<B_ * N_ / BN_PER_BLK, 512>>>(Y, pg, pbe, out);
}